// round 4
// baseline (speedup 1.0000x reference)
#include <cuda_runtime.h>
#include <math.h>

#define NMAX 50000
#define KD 128
typedef unsigned long long u64;

__device__ float g_h[(size_t)NMAX * KD];
__device__ float g_agg[(size_t)NMAX * KD];
__device__ float g_o0[(size_t)NMAX * KD];

// ---- packed fp32x2 helpers ----
__device__ __forceinline__ u64 dup2(float x) {
    union { float2 f; u64 u; } c;
    c.f = make_float2(x, x);
    return c.u;
}
__device__ __forceinline__ void fma2(u64& d, u64 a, u64 b) {
    asm("fma.rn.f32x2 %0, %1, %2, %3;" : "=l"(d) : "l"(a), "l"(b), "l"(d));
}
__device__ __forceinline__ float2 unpk(u64 v) {
    union { u64 u; float2 f; } c;
    c.u = v;
    return c.f;
}

// ---- smem swizzles (no padding, conflict-free reads, <=4-way writes) ----
// A tile: As[k][row], 128 x 64 floats. phys unit = (row>>2) ^ xa(k), xa = ((k>>2)&7)<<1
__device__ __forceinline__ int xa_of(int k) { return ((k >> 2) & 7) << 1; }
// W tile: Ws[k][o], 128 x FOUT floats. phys unit = (o>>2) ^ xw(k)
__device__ __forceinline__ int xw_of(int k) { return (k & 7) ^ (((k >> 3) & 3) << 1); }

// =====================================================================
// pool GEMM + fused row L2-norm, FFMA2 8x8 tile:
//   H[m,o] = relu( inv_norm[m] * (X[m,:] . W[o,:]) + B[o] )
// block: 64 rows x 128 cols, 128 threads (4 warps = 2m x 2n)
// =====================================================================
__global__ __launch_bounds__(128, 2)
void pool_gemm(const float* __restrict__ X, const float* __restrict__ W,
               const float* __restrict__ B, float* __restrict__ H, int n)
{
    extern __shared__ float sm[];
    float* As   = sm;                  // 128*64
    float* Ws   = As + KD * 64;        // 128*128
    float* invn = Ws + KD * 128;       // 64

    const int t = threadIdx.x;
    const int warp = t >> 5, lane = t & 31;
    const int m0 = blockIdx.x * 64;

    // stage W (float4 along k, swizzled scalar stores)
    for (int i = t; i < 128 * 32; i += 128) {
        int o = i >> 5;
        int k4 = (i & 31) << 2;
        float4 w = reinterpret_cast<const float4*>(W)[i];
        float wv[4] = {w.x, w.y, w.z, w.w};
        #pragma unroll
        for (int j = 0; j < 4; ++j) {
            int k = k4 + j;
            Ws[k * 128 + ((((o >> 2) ^ xw_of(k)) << 2) | (o & 3))] = wv[j];
        }
    }

    // stage A + row norms (each warp: 16 rows)
    {
        const int xa = (lane & 7) << 1;            // xa_of(lane*4)
        #pragma unroll
        for (int i = 0; i < 16; ++i) {
            int row = warp * 16 + i;
            int m = m0 + row;
            float4 v = make_float4(0.f, 0.f, 0.f, 0.f);
            if (m < n) v = reinterpret_cast<const float4*>(X)[(size_t)m * 32 + lane];
            float s = v.x * v.x + v.y * v.y + v.z * v.z + v.w * v.w;
            #pragma unroll
            for (int off = 16; off > 0; off >>= 1)
                s += __shfl_xor_sync(0xffffffffu, s, off);
            if (lane == 0) invn[row] = 1.0f / fmaxf(sqrtf(s), 1e-12f);
            int base = (lane * 4) * 64 + (((row >> 2) ^ xa) << 2) + (row & 3);
            As[base]       = v.x;
            As[base + 64]  = v.y;
            As[base + 128] = v.z;
            As[base + 192] = v.w;
        }
    }
    __syncthreads();

    const int wr = warp & 1, wc = warp >> 1;
    const int lr = lane >> 3, lc = lane & 7;
    const int mrow = wr * 32 + lr * 8;
    const int c0 = wc * 64 + lc * 4;      // thread cols: c0..c0+3, c0+32..c0+35
    const int au = mrow >> 2;
    const int wu = c0 >> 2;

    u64 acc[4][8];
    #pragma unroll
    for (int i = 0; i < 4; ++i)
        #pragma unroll
        for (int j = 0; j < 8; ++j) acc[i][j] = 0ull;

    #pragma unroll 4
    for (int k = 0; k < KD; ++k) {
        const float* pa = As + k * 64 + ((au ^ xa_of(k)) << 2);
        ulonglong2 q0 = *reinterpret_cast<const ulonglong2*>(pa);
        ulonglong2 q1 = *reinterpret_cast<const ulonglong2*>(pa + 4);
        u64 ap[4] = {q0.x, q0.y, q1.x, q1.y};

        const float* pw = Ws + k * 128 + ((wu ^ xw_of(k)) << 2);
        float4 w0 = *reinterpret_cast<const float4*>(pw);
        float4 w1 = *reinterpret_cast<const float4*>(pw + 32);
        u64 bd[8] = {dup2(w0.x), dup2(w0.y), dup2(w0.z), dup2(w0.w),
                     dup2(w1.x), dup2(w1.y), dup2(w1.z), dup2(w1.w)};
        #pragma unroll
        for (int i = 0; i < 4; ++i)
            #pragma unroll
            for (int j = 0; j < 8; ++j)
                fma2(acc[i][j], ap[i], bd[j]);
    }

    float bs[8];
    #pragma unroll
    for (int j = 0; j < 4; ++j) { bs[j] = B[c0 + j]; bs[j + 4] = B[c0 + 32 + j]; }

    #pragma unroll
    for (int r = 0; r < 8; ++r) {
        int m = m0 + mrow + r;
        if (m >= n) continue;
        float inv = invn[mrow + r];
        int mi = r >> 1, p = r & 1;
        float v[8];
        #pragma unroll
        for (int j = 0; j < 8; ++j) {
            float2 f = unpk(acc[mi][j]);
            v[j] = fmaxf(fmaf(p ? f.y : f.x, inv, bs[j]), 0.f);
        }
        float4 r0 = make_float4(v[0], v[1], v[2], v[3]);
        float4 r1 = make_float4(v[4], v[5], v[6], v[7]);
        reinterpret_cast<float4*>(H)[(size_t)m * 32 + (c0 >> 2)]     = r0;
        reinterpret_cast<float4*>(H)[(size_t)m * 32 + (c0 >> 2) + 8] = r1;
    }
}

// =====================================================================
// fused fc, two-pass, FFMA2:
//   pass 0: acc += H . W1^T   pass 1: acc += sqrt(G) . W2^T
//   OUT = act(acc + B1 + B2)
// =====================================================================
template <int FOUT, bool RELU, int MINB>
__global__ __launch_bounds__(128, MINB)
void fc_gemm(const float* __restrict__ Hin, const float* __restrict__ G,
             const float* __restrict__ W1, const float* __restrict__ W2,
             const float* __restrict__ B1, const float* __restrict__ B2,
             float* __restrict__ OUT, int n)
{
    constexpr int NG = FOUT / 64;     // float4-groups per thread (2 or 1)
    extern __shared__ float sm[];
    float* As = sm;                   // 128*64
    float* Ws = As + KD * 64;         // 128*FOUT

    const int t = threadIdx.x;
    const int warp = t >> 5, lane = t & 31;
    const int m0 = blockIdx.x * 64;

    const int wr = warp & 1, wc = warp >> 1;
    const int lr = lane >> 3, lc = lane & 7;
    const int mrow = wr * 32 + lr * 8;
    const int c0 = wc * (FOUT / 2) + lc * 4;
    const int au = mrow >> 2;
    const int wu = c0 >> 2;

    u64 acc[4][NG * 4];
    #pragma unroll
    for (int i = 0; i < 4; ++i)
        #pragma unroll
        for (int j = 0; j < NG * 4; ++j) acc[i][j] = 0ull;

    #pragma unroll
    for (int pass = 0; pass < 2; ++pass) {
        const float* Ain = pass ? G : Hin;
        const float* Wm  = pass ? W2 : W1;
        if (pass) __syncthreads();    // protect smem before restaging

        for (int i = t; i < FOUT * 32; i += 128) {
            int o = i >> 5;
            int k4 = (i & 31) << 2;
            float4 w = reinterpret_cast<const float4*>(Wm)[i];
            float wv[4] = {w.x, w.y, w.z, w.w};
            #pragma unroll
            for (int j = 0; j < 4; ++j) {
                int k = k4 + j;
                Ws[k * FOUT + ((((o >> 2) ^ xw_of(k)) << 2) | (o & 3))] = wv[j];
            }
        }

        {
            const int xa = (lane & 7) << 1;
            #pragma unroll
            for (int i = 0; i < 16; ++i) {
                int row = warp * 16 + i;
                int m = m0 + row;
                float4 v = make_float4(0.f, 0.f, 0.f, 0.f);
                if (m < n) v = reinterpret_cast<const float4*>(Ain)[(size_t)m * 32 + lane];
                if (pass) {
                    v.x = sqrtf(v.x); v.y = sqrtf(v.y);
                    v.z = sqrtf(v.z); v.w = sqrtf(v.w);
                }
                int base = (lane * 4) * 64 + (((row >> 2) ^ xa) << 2) + (row & 3);
                As[base]       = v.x;
                As[base + 64]  = v.y;
                As[base + 128] = v.z;
                As[base + 192] = v.w;
            }
        }
        __syncthreads();

        #pragma unroll 4
        for (int k = 0; k < KD; ++k) {
            const float* pa = As + k * 64 + ((au ^ xa_of(k)) << 2);
            ulonglong2 q0 = *reinterpret_cast<const ulonglong2*>(pa);
            ulonglong2 q1 = *reinterpret_cast<const ulonglong2*>(pa + 4);
            u64 ap[4] = {q0.x, q0.y, q1.x, q1.y};

            const float* pw = Ws + k * FOUT + ((wu ^ xw_of(k)) << 2);
            u64 bd[NG * 4];
            #pragma unroll
            for (int g = 0; g < NG; ++g) {
                float4 w = *reinterpret_cast<const float4*>(pw + g * 32);
                bd[4*g+0] = dup2(w.x); bd[4*g+1] = dup2(w.y);
                bd[4*g+2] = dup2(w.z); bd[4*g+3] = dup2(w.w);
            }
            #pragma unroll
            for (int i = 0; i < 4; ++i)
                #pragma unroll
                for (int j = 0; j < NG * 4; ++j)
                    fma2(acc[i][j], ap[i], bd[j]);
        }
    }

    float bs[NG * 4];
    #pragma unroll
    for (int g = 0; g < NG; ++g)
        #pragma unroll
        for (int j = 0; j < 4; ++j) {
            int c = c0 + g * 32 + j;
            bs[4*g+j] = B1[c] + B2[c];
        }

    #pragma unroll
    for (int r = 0; r < 8; ++r) {
        int m = m0 + mrow + r;
        if (m >= n) continue;
        int mi = r >> 1, p = r & 1;
        #pragma unroll
        for (int g = 0; g < NG; ++g) {
            float v[4];
            #pragma unroll
            for (int j = 0; j < 4; ++j) {
                float2 f = unpk(acc[mi][4*g+j]);
                v[j] = (p ? f.y : f.x) + bs[4*g+j];
                if (RELU) v[j] = fmaxf(v[j], 0.f);
            }
            reinterpret_cast<float4*>(OUT)[(size_t)m * (FOUT / 4) + (c0 >> 2) + g * 8] =
                make_float4(v[0], v[1], v[2], v[3]);
        }
    }
}

// =====================================================================
// SpMM scatter: AGG[dst,:] += val * H[src,:]^2   (warp/edge, red.v4)
// =====================================================================
__global__ __launch_bounds__(256)
void spmm_kernel(const int* __restrict__ src, const int* __restrict__ dst,
                 const float* __restrict__ val, const float* __restrict__ Hm,
                 float* __restrict__ AGG, int E)
{
    int gw = (int)((blockIdx.x * 256u + threadIdx.x) >> 5);
    int lane = threadIdx.x & 31;
    if (gw >= E) return;
    int s = src[gw];
    int d = dst[gw];
    float v = val[gw];
    float4 h = reinterpret_cast<const float4*>(Hm)[(size_t)s * 32 + lane];
    float4 r;
    r.x = h.x * h.x * v;
    r.y = h.y * h.y * v;
    r.z = h.z * h.z * v;
    r.w = h.w * h.w * v;
    float* p = AGG + (size_t)d * 128 + lane * 4;
    asm volatile("red.global.add.v4.f32 [%0], {%1, %2, %3, %4};"
                 :: "l"(p), "f"(r.x), "f"(r.y), "f"(r.z), "f"(r.w) : "memory");
}

__global__ void zero_kernel(float4* __restrict__ p, int n4)
{
    int i = blockIdx.x * blockDim.x + threadIdx.x;
    int stride = gridDim.x * blockDim.x;
    float4 z = make_float4(0.f, 0.f, 0.f, 0.f);
    for (; i < n4; i += stride) p[i] = z;
}

// =====================================================================
extern "C" void kernel_launch(void* const* d_in, const int* in_sizes, int n_in,
                              void* d_out, int out_size)
{
    const float* x     = (const float*)d_in[0];
    const int*   esrc  = (const int*)  d_in[1];
    const int*   edst  = (const int*)  d_in[2];
    const float* eval_ = (const float*)d_in[3];
    const float* pw0   = (const float*)d_in[4];
    const float* pb0   = (const float*)d_in[5];
    const float* f1w0  = (const float*)d_in[6];
    const float* f1b0  = (const float*)d_in[7];
    const float* f2w0  = (const float*)d_in[8];
    const float* f2b0  = (const float*)d_in[9];
    const float* pw1   = (const float*)d_in[10];
    const float* pb1   = (const float*)d_in[11];
    const float* f1w1  = (const float*)d_in[12];
    const float* f1b1  = (const float*)d_in[13];
    const float* f2w1  = (const float*)d_in[14];
    const float* f2b1  = (const float*)d_in[15];
    float* out = (float*)d_out;

    int n = in_sizes[0] / KD;
    int E = in_sizes[1];

    float *hP, *aP, *oP;
    cudaGetSymbolAddress((void**)&hP, g_h);
    cudaGetSymbolAddress((void**)&aP, g_agg);
    cudaGetSymbolAddress((void**)&oP, g_o0);

    const int POOL_SMEM  = (KD * 64 + KD * 128 + 64) * 4;  // 98,560 B
    const int FC128_SMEM = (KD * 64 + KD * 128) * 4;       // 98,304 B
    const int FC64_SMEM  = (KD * 64 + KD * 64) * 4;        // 65,536 B
    cudaFuncSetAttribute(pool_gemm, cudaFuncAttributeMaxDynamicSharedMemorySize, POOL_SMEM);
    cudaFuncSetAttribute((const void*)fc_gemm<128, true, 2>,
                         cudaFuncAttributeMaxDynamicSharedMemorySize, FC128_SMEM);
    cudaFuncSetAttribute((const void*)fc_gemm<64, false, 3>,
                         cudaFuncAttributeMaxDynamicSharedMemorySize, FC64_SMEM);

    int mb = (n + 63) / 64;
    int sb = (int)(((long long)E * 32 + 255) / 256);

    // ---- layer 0 ----
    pool_gemm<<<mb, 128, POOL_SMEM>>>(x, pw0, pb0, hP, n);
    zero_kernel<<<2048, 256>>>((float4*)aP, n * 32);
    spmm_kernel<<<sb, 256>>>(esrc, edst, eval_, hP, aP, E);
    fc_gemm<128, true, 2><<<mb, 128, FC128_SMEM>>>(hP, aP, f1w0, f2w0, f1b0, f2b0, oP, n);

    // ---- layer 1 ----
    pool_gemm<<<mb, 128, POOL_SMEM>>>(oP, pw1, pb1, hP, n);
    zero_kernel<<<2048, 256>>>((float4*)aP, n * 32);
    spmm_kernel<<<sb, 256>>>(esrc, edst, eval_, hP, aP, E);
    fc_gemm<64, false, 3><<<mb, 128, FC64_SMEM>>>(hP, aP, f1w1, f2w1, f1b1, f2b1, out, n);
}